// round 9
// baseline (speedup 1.0000x reference)
#include <cuda_runtime.h>
#include <math.h>

// ---------------------------------------------------------------------------
// Shapes
// B=16, H=W=256, C=1, LOC_C=31
// x1 (after conv1+pool): 16x128x128x8
// x2 (after conv2+pool): 16x64x64x16
// x3 (after conv3+pool): 16x32x32x31   (== x_intermediate, NHWC flatten)
// feat = 32*32*31 = 31744 = 496 * 64
// out: 16x256x256x32
// ---------------------------------------------------------------------------

#define BN_EPS 1e-3f

__device__ float g_x1[16 * 128 * 128 * 8];     // 8 MB
__device__ float g_x2[16 * 64 * 64 * 16];      // 4 MB
__device__ float g_x3[16 * 32 * 32 * 31];      // 2 MB  (packed, for d1)
__device__ float g_x3p[16 * 32 * 32 * 32];     // 2 MB  (padded+shifted, sampler)
__device__ float g_part[496 * 16 * 64];        // 2 MB  (split-K partials for d1)
__device__ float g_h1[16 * 64];                // relu(d1 output)
__device__ float g_theta[16 * 6];              // affine params

// ---------------------------------------------------------------------------
// K1: conv1 (3x3, 1->8, SAME) + ReLU + maxpool2  -> g_x1
// ---------------------------------------------------------------------------
__global__ __launch_bounds__(256) void k_conv1(
    const float* __restrict__ x,       // (16,256,256,1)
    const float* __restrict__ k1,      // (3,3,1,8)
    const float* __restrict__ b1)      // (8,)
{
    __shared__ float s_x[34 * 34];
    __shared__ __align__(16) float s_w[72];
    __shared__ float s_b[8];
    int tid = threadIdx.x;
    int bidx = blockIdx.x;
    int b  = bidx >> 6;
    int t  = bidx & 63;
    int ty0 = (t >> 3) * 16;
    int tx0 = (t & 7) * 16;

    if (tid < 72) s_w[tid] = k1[tid];
    if (tid < 8)  s_b[tid] = b1[tid];

    const float* xb = x + b * 65536;
    int iy0 = 2 * ty0 - 1, ix0 = 2 * tx0 - 1;
    for (int p = tid; p < 34 * 34; p += 256) {
        int r = p / 34, c = p % 34;
        int gy = iy0 + r, gx = ix0 + c;
        s_x[p] = (gy >= 0 && gy < 256 && gx >= 0 && gx < 256)
                 ? xb[gy * 256 + gx] : 0.f;
    }
    __syncthreads();

    int ly = tid >> 4, lx = tid & 15;

    float win[4][4];
#pragma unroll
    for (int r = 0; r < 4; r++)
#pragma unroll
        for (int c = 0; c < 4; c++)
            win[r][c] = s_x[(2 * ly + r) * 34 + (2 * lx + c)];

    float s[4][8];
#pragma unroll
    for (int p = 0; p < 4; p++)
#pragma unroll
        for (int co = 0; co < 8; co++) s[p][co] = 0.f;

#pragma unroll
    for (int ky = 0; ky < 3; ky++) {
#pragma unroll
        for (int kx = 0; kx < 3; kx++) {
            float4 w0 = *(const float4*)&s_w[(ky * 3 + kx) * 8];
            float4 w1 = *(const float4*)&s_w[(ky * 3 + kx) * 8 + 4];
            float w[8] = {w0.x, w0.y, w0.z, w0.w, w1.x, w1.y, w1.z, w1.w};
#pragma unroll
            for (int dy = 0; dy < 2; dy++) {
#pragma unroll
                for (int dx = 0; dx < 2; dx++) {
                    float v = win[dy + ky][dx + kx];
#pragma unroll
                    for (int co = 0; co < 8; co++)
                        s[dy * 2 + dx][co] += v * w[co];
                }
            }
        }
    }

    float o[8];
#pragma unroll
    for (int co = 0; co < 8; co++) {
        float m = fmaxf(fmaxf(s[0][co], s[1][co]), fmaxf(s[2][co], s[3][co]));
        o[co] = fmaxf(m + s_b[co], 0.f);
    }
    int py = ty0 + ly, px = tx0 + lx;
    float* op = g_x1 + ((size_t)(b * 128 + py) * 128 + px) * 8;
    *(float4*)op       = make_float4(o[0], o[1], o[2], o[3]);
    *(float4*)(op + 4) = make_float4(o[4], o[5], o[6], o[7]);
}

// ---------------------------------------------------------------------------
// K2: conv2 (3x3, 8->16) + ReLU + pool -> g_x2
// ---------------------------------------------------------------------------
__global__ __launch_bounds__(256) void k_conv2(
    const float* __restrict__ k2,      // (3,3,8,16)
    const float* __restrict__ b2)      // (16,)
{
    __shared__ __align__(16) float s_in[18 * 18 * 8];  // 2592 floats
    __shared__ __align__(16) float s_w[1152];
    __shared__ float s_b[16];

    int tid = threadIdx.x;
    int bidx = blockIdx.x;
    int b  = bidx >> 6;
    int t  = bidx & 63;
    int ty0 = (t >> 3) * 8;
    int tx0 = (t & 7) * 8;

    for (int i = tid; i < 1152; i += 256) s_w[i] = k2[i];
    if (tid < 16) s_b[tid] = b2[tid];

    int iy0 = 2 * ty0 - 1, ix0 = 2 * tx0 - 1;
    for (int p = tid; p < 18 * 18; p += 256) {
        int r = p / 18, c = p % 18;
        int gy = iy0 + r, gx = ix0 + c;
        float* dst = &s_in[p * 8];
        if (gy >= 0 && gy < 128 && gx >= 0 && gx < 128) {
            const float* src = g_x1 + ((size_t)(b * 128 + gy) * 128 + gx) * 8;
            *(float4*)dst       = *(const float4*)src;
            *(float4*)(dst + 4) = *(const float4*)(src + 4);
        } else {
            *(float4*)dst       = make_float4(0, 0, 0, 0);
            *(float4*)(dst + 4) = make_float4(0, 0, 0, 0);
        }
    }
    __syncthreads();

    int pix = tid >> 2, cog = tid & 3, cb = cog * 4;
    int ly = pix >> 3, lx = pix & 7;

    float acc[4][4];
#pragma unroll
    for (int p = 0; p < 4; p++)
#pragma unroll
        for (int k = 0; k < 4; k++) acc[p][k] = 0.f;

#pragma unroll
    for (int ky = 0; ky < 3; ky++) {
#pragma unroll
        for (int kx = 0; kx < 3; kx++) {
            const float* wtap = &s_w[(ky * 3 + kx) * 128 + cb];
#pragma unroll
            for (int ciq = 0; ciq < 2; ciq++) {
                float iv[4][4];
#pragma unroll
                for (int dy = 0; dy < 2; dy++) {
#pragma unroll
                    for (int dx = 0; dx < 2; dx++) {
                        float4 v = *(const float4*)&s_in[
                            ((2 * ly + dy + ky) * 18 + (2 * lx + dx + kx)) * 8 + ciq * 4];
                        int p = dy * 2 + dx;
                        iv[p][0] = v.x; iv[p][1] = v.y; iv[p][2] = v.z; iv[p][3] = v.w;
                    }
                }
#pragma unroll
                for (int c = 0; c < 4; c++) {
                    float4 w = *(const float4*)(wtap + (ciq * 4 + c) * 16);
#pragma unroll
                    for (int p = 0; p < 4; p++) {
                        float v = iv[p][c];
                        acc[p][0] += v * w.x; acc[p][1] += v * w.y;
                        acc[p][2] += v * w.z; acc[p][3] += v * w.w;
                    }
                }
            }
        }
    }

    float m[4];
#pragma unroll
    for (int k = 0; k < 4; k++)
        m[k] = fmaxf(fmaxf(acc[0][k], acc[1][k]), fmaxf(acc[2][k], acc[3][k]));

    int py = ty0 + ly, px = tx0 + lx;
    float* op = g_x2 + ((size_t)(b * 64 + py) * 64 + px) * 16 + cb;
    *(float4*)op = make_float4(fmaxf(m[0] + s_b[cb], 0.f),
                               fmaxf(m[1] + s_b[cb + 1], 0.f),
                               fmaxf(m[2] + s_b[cb + 2], 0.f),
                               fmaxf(m[3] + s_b[cb + 3], 0.f));
}

// ---------------------------------------------------------------------------
// K3: conv3 (3x3, 16->31) + ReLU + pool -> g_x3 (packed) + g_x3p (padded)
// g_x3p layout: [b][cell][32] where slot c holds OUTPUT channel c
// (slot 0 = 0, slots 1..31 = conv3 channels 0..30).
// ---------------------------------------------------------------------------
__global__ __launch_bounds__(256) void k_conv3(
    const float* __restrict__ k3,      // (3,3,16,31)
    const float* __restrict__ b3)      // (31,)
{
    __shared__ __align__(16) float s_in[10 * 18 * 16];  // 2880 floats
    __shared__ __align__(16) float s_w[9 * 16 * 32];    // 4608 floats (co padded)
    __shared__ float s_b[32];

    int tid = threadIdx.x;
    int bidx = blockIdx.x;
    int b  = bidx >> 5;
    int t  = bidx & 31;
    int ty0 = (t >> 2) * 4;
    int tx0 = (t & 3) * 8;

    for (int i = tid; i < 4608; i += 256) {
        int tap = i >> 9;
        int rem = i & 511;
        int ci = rem >> 5, co = rem & 31;
        s_w[i] = (co < 31) ? k3[tap * 496 + ci * 31 + co] : 0.f;
    }
    if (tid < 32) s_b[tid] = (tid < 31) ? b3[tid] : 0.f;

    int iy0 = 2 * ty0 - 1, ix0 = 2 * tx0 - 1;
    for (int p = tid; p < 10 * 18; p += 256) {
        int r = p / 18, c = p % 18;
        int gy = iy0 + r, gx = ix0 + c;
        float* dst = &s_in[p * 16];
        if (gy >= 0 && gy < 64 && gx >= 0 && gx < 64) {
            const float* src = g_x2 + ((size_t)(b * 64 + gy) * 64 + gx) * 16;
#pragma unroll
            for (int q = 0; q < 4; q++)
                *(float4*)(dst + q * 4) = *(const float4*)(src + q * 4);
        } else {
#pragma unroll
            for (int q = 0; q < 4; q++)
                *(float4*)(dst + q * 4) = make_float4(0, 0, 0, 0);
        }
    }
    __syncthreads();

    int pix = tid >> 3, cog = tid & 7, cb = cog * 4;
    int ly = pix >> 3, lx = pix & 7;

    float acc[4][4];
#pragma unroll
    for (int p = 0; p < 4; p++)
#pragma unroll
        for (int k = 0; k < 4; k++) acc[p][k] = 0.f;

#pragma unroll
    for (int ky = 0; ky < 3; ky++) {
#pragma unroll
        for (int kx = 0; kx < 3; kx++) {
            const float* wtap = &s_w[(ky * 3 + kx) * 512 + cb];
#pragma unroll
            for (int ciq = 0; ciq < 4; ciq++) {
                float iv[4][4];
#pragma unroll
                for (int dy = 0; dy < 2; dy++) {
#pragma unroll
                    for (int dx = 0; dx < 2; dx++) {
                        float4 v = *(const float4*)&s_in[
                            ((2 * ly + dy + ky) * 18 + (2 * lx + dx + kx)) * 16 + ciq * 4];
                        int p = dy * 2 + dx;
                        iv[p][0] = v.x; iv[p][1] = v.y; iv[p][2] = v.z; iv[p][3] = v.w;
                    }
                }
#pragma unroll
                for (int c = 0; c < 4; c++) {
                    float4 w = *(const float4*)(wtap + (ciq * 4 + c) * 32);
#pragma unroll
                    for (int p = 0; p < 4; p++) {
                        float v = iv[p][c];
                        acc[p][0] += v * w.x; acc[p][1] += v * w.y;
                        acc[p][2] += v * w.z; acc[p][3] += v * w.w;
                    }
                }
            }
        }
    }

    float m[4];
#pragma unroll
    for (int k = 0; k < 4; k++)
        m[k] = fmaxf(fmaxf(acc[0][k], acc[1][k]), fmaxf(acc[2][k], acc[3][k]));

    int py = ty0 + ly, px = tx0 + lx;
    int cell = (b * 32 + py) * 32 + px;
    float* op  = g_x3  + (size_t)cell * 31;
    float* opp = g_x3p + (size_t)cell * 32;
    if (cog == 0) opp[0] = 0.f;
#pragma unroll
    for (int k = 0; k < 4; k++) {
        int co = cb + k;
        if (co < 31) {
            float v = fmaxf(m[k] + s_b[co], 0.f);
            op[co] = v;
            opp[co + 1] = v;
        }
    }
}

// ---------------------------------------------------------------------------
// K5: d1 split-K with fused BN affine. 496 blocks, 64-feature slices.
// ---------------------------------------------------------------------------
__global__ __launch_bounds__(256) void k_d1(
    const float* __restrict__ d1k,
    const float* __restrict__ gamma, const float* __restrict__ beta,
    const float* __restrict__ mean,  const float* __restrict__ var)
{
    __shared__ __align__(16) float ks[64 * 64];   // 16 KB
    __shared__ __align__(16) float gs[16 * 64];   //  4 KB
    __shared__ float s_sc[64], s_sh[64];
    int tid = threadIdx.x;
    int p = blockIdx.x;

    const float4* kbase = (const float4*)(d1k + (size_t)p * 4096);
    float4* ks4 = (float4*)ks;
#pragma unroll
    for (int i = 0; i < 4; i++) ks4[tid + i * 256] = kbase[tid + i * 256];

    if (tid < 64) {
        int f = p * 64 + tid;
        float sc = rsqrtf(var[f] + BN_EPS) * gamma[f];
        s_sc[tid] = sc;
        s_sh[tid] = beta[f] - mean[f] * sc;
    }
    __syncthreads();
    for (int i = tid; i < 1024; i += 256) {
        int bb = i >> 6, ii = i & 63;
        gs[i] = g_x3[bb * 31744 + p * 64 + ii] * s_sc[ii] + s_sh[ii];
    }
    __syncthreads();

    int j = tid & 63, bq = tid >> 6;
    float a0 = 0.f, a1 = 0.f, a2 = 0.f, a3 = 0.f;
#pragma unroll 8
    for (int i = 0; i < 64; i++) {
        float kv = ks[i * 64 + j];
        a0 += gs[bq * 64 + i]        * kv;
        a1 += gs[(bq + 4) * 64 + i]  * kv;
        a2 += gs[(bq + 8) * 64 + i]  * kv;
        a3 += gs[(bq + 12) * 64 + i] * kv;
    }
    g_part[((size_t)p * 16 + bq)      * 64 + j] = a0;
    g_part[((size_t)p * 16 + bq + 4)  * 64 + j] = a1;
    g_part[((size_t)p * 16 + bq + 8)  * 64 + j] = a2;
    g_part[((size_t)p * 16 + bq + 12) * 64 + j] = a3;
}

// K6: reduce partials + bias + relu -> g_h1. Warp per (b,j), shuffle reduce.
__global__ __launch_bounds__(256) void k_d1red(const float* __restrict__ d1b)
{
    int gwarp = (blockIdx.x * 256 + threadIdx.x) >> 5;   // 0..1023
    int lane = threadIdx.x & 31;
    int b = gwarp >> 6, j = gwarp & 63;
    float s = 0.f;
    for (int p = lane; p < 496; p += 32)
        s += g_part[((size_t)p * 16 + b) * 64 + j];
#pragma unroll
    for (int o = 16; o; o >>= 1) s += __shfl_xor_sync(0xFFFFFFFFu, s, o);
    if (lane == 0) g_h1[b * 64 + j] = fmaxf(s + d1b[j], 0.f);
}

// K7: d2 (64->96, relu) + d3 (96->6) -> g_theta. One block per batch.
__global__ __launch_bounds__(128) void k_d23(
    const float* __restrict__ d2k, const float* __restrict__ d2b,
    const float* __restrict__ d3k, const float* __restrict__ d3b)
{
    __shared__ float h1s[64];
    __shared__ float h2s[96];
    int tid = threadIdx.x;
    int b = blockIdx.x;
    if (tid < 64) h1s[tid] = g_h1[b * 64 + tid];
    __syncthreads();
    if (tid < 96) {
        float s = d2b[tid];
#pragma unroll 8
        for (int i = 0; i < 64; i++) s += h1s[i] * d2k[i * 96 + tid];
        h2s[tid] = fmaxf(s, 0.f);
    }
    __syncthreads();
    if (tid < 6) {
        float s = d3b[tid];
#pragma unroll 8
        for (int j = 0; j < 96; j++) s += h2s[j] * d3k[j * 6 + tid];
        g_theta[b * 6 + tid] = s;
    }
}

// ---------------------------------------------------------------------------
// K8: fused grid-gen + bilinear sampler + leaky relu, smem-tiled coarse cells.
// Block = (batch, 32x32 output tile). The affine map is linear, so the tile's
// sample bbox comes from its 4 corners. If the needed coarse-cell rectangle
// fits in smem (<=320 cells = 40KB), stage it once and sample from smem;
// otherwise fall back to direct global gathers (block-uniform branch).
// Lane layout: 8 lanes per pixel (channel quads), 4 pixels per warp.
// ---------------------------------------------------------------------------
#define SMP_CAP 320

__global__ __launch_bounds__(256) void k_sampler(
    const float* __restrict__ x,       // (16,256,256,1)
    float* __restrict__ out)           // (16,256,256,32)
{
    __shared__ __align__(16) float s_cells[SMP_CAP * 32];  // 40 KB

    int bidx = blockIdx.x;             // 16 * 64
    int b  = bidx >> 6;
    int t  = bidx & 63;
    int ty0 = (t >> 3) * 32;
    int tx0 = (t & 7) * 32;
    int tid = threadIdx.x;

    float th0 = g_theta[b * 6 + 0];
    float th1 = g_theta[b * 6 + 1];
    float th2 = g_theta[b * 6 + 2];
    float th3 = g_theta[b * 6 + 3];
    float th4 = g_theta[b * 6 + 4];
    float th5 = g_theta[b * 6 + 5];

    // fx(ox,oy) = 0.5*((gx*th0 + gy*th3 + th2 + 1)*255), gx = ox/255*2-1
    // Linear in (ox,oy): evaluate at 4 tile corners for the bbox.
    float fxm = 1e30f, fxM = -1e30f, fym = 1e30f, fyM = -1e30f;
#pragma unroll
    for (int cy = 0; cy < 2; cy++) {
#pragma unroll
        for (int cx = 0; cx < 2; cx++) {
            float ox = (float)(tx0 + cx * 31);
            float oy = (float)(ty0 + cy * 31);
            float gx = ox * (2.f / 255.f) - 1.f;
            float gy = oy * (2.f / 255.f) - 1.f;
            float fx = 0.5f * ((gx * th0 + gy * th3 + th2 + 1.f) * 255.f);
            float fy = 0.5f * ((gx * th1 + gy * th4 + th5 + 1.f) * 255.f);
            fxm = fminf(fxm, fx); fxM = fmaxf(fxM, fx);
            fym = fminf(fym, fy); fyM = fmaxf(fyM, fy);
        }
    }
    int ximin = min(max((int)floorf(fxm), 0), 255);
    int ximax = min(max((int)floorf(fxM) + 1, 0), 255);
    int yimin = min(max((int)floorf(fym), 0), 255);
    int yimax = min(max((int)floorf(fyM) + 1, 0), 255);
    int cxmin = ximin >> 3, cxmax = ximax >> 3;
    int cymin = yimin >> 3, cymax = yimax >> 3;
    int nx = cxmax - cxmin + 1;
    int ny = cymax - cymin + 1;
    int ncells = nx * ny;
    bool fast = (ncells <= SMP_CAP);

    if (fast) {
        const float* src = g_x3p + (size_t)b * 32768;
        float4* sc4 = (float4*)s_cells;
        int total = ncells * 8;                  // float4s
        for (int i = tid; i < total; i += 256) {
            int cell = i >> 3, q = i & 7;
            int cy = cymin + cell / nx;
            int cx = cxmin + cell % nx;
            sc4[i] = ((const float4*)(src + ((size_t)(cy * 32 + cx)) * 32))[q];
        }
        __syncthreads();
    }

    int tq = tid & 7;                  // channel quad
    int pp = tid >> 3;                 // pixel-in-row (0..31)
    int ox = tx0 + pp;
    float gx = (float)ox * (2.f / 255.f) - 1.f;
    const float* xb = x + (size_t)b * 65536;
    const float* xp = g_x3p + (size_t)b * 32768 + 4 * tq;

    for (int pass = 0; pass < 32; pass++) {
        int oy = ty0 + pass;
        float gy = (float)oy * (2.f / 255.f) - 1.f;
        float tgx = gx * th0 + gy * th3 + th2;
        float tgy = gx * th1 + gy * th4 + th5;

        float fx = 0.5f * ((tgx + 1.f) * 255.f);
        float fy = 0.5f * ((tgy + 1.f) * 255.f);
        float x0f = floorf(fx), x1f = x0f + 1.f;
        float y0f = floorf(fy), y1f = y0f + 1.f;
        x0f = fminf(fmaxf(x0f, 0.f), 255.f);
        x1f = fminf(fmaxf(x1f, 0.f), 255.f);
        y0f = fminf(fmaxf(y0f, 0.f), 255.f);
        y1f = fminf(fmaxf(y1f, 0.f), 255.f);
        float wa = (x1f - fx) * (y1f - fy);
        float wb = (x1f - fx) * (fy - y0f);
        float wc = (fx - x0f) * (y1f - fy);
        float wd = (fx - x0f) * (fy - y0f);
        int xi0 = (int)x0f, xi1 = (int)x1f, yi0 = (int)y0f, yi1 = (int)y1f;

        int cy0 = yi0 >> 3, cy1 = yi1 >> 3, cx0 = xi0 >> 3, cx1 = xi1 >> 3;

        float4 va, vb, vc, vd;
        if (fast) {
            int ia = ((cy0 - cymin) * nx + (cx0 - cxmin)) * 32 + 4 * tq;
            int ib = ((cy1 - cymin) * nx + (cx0 - cxmin)) * 32 + 4 * tq;
            int ic = ((cy0 - cymin) * nx + (cx1 - cxmin)) * 32 + 4 * tq;
            int id = ((cy1 - cymin) * nx + (cx1 - cxmin)) * 32 + 4 * tq;
            va = *(const float4*)&s_cells[ia];
            vb = *(const float4*)&s_cells[ib];
            vc = *(const float4*)&s_cells[ic];
            vd = *(const float4*)&s_cells[id];
        } else {
            va = *(const float4*)(xp + (size_t)(cy0 * 32 + cx0) * 32);
            vb = *(const float4*)(xp + (size_t)(cy1 * 32 + cx0) * 32);
            vc = *(const float4*)(xp + (size_t)(cy0 * 32 + cx1) * 32);
            vd = *(const float4*)(xp + (size_t)(cy1 * 32 + cx1) * 32);
        }

        float4 val;
        val.x = wa * va.x + wb * vb.x + wc * vc.x + wd * vd.x;
        val.y = wa * va.y + wb * vb.y + wc * vc.y + wd * vd.y;
        val.z = wa * va.z + wb * vb.z + wc * vc.z + wd * vd.z;
        val.w = wa * va.w + wb * vb.w + wc * vc.w + wd * vd.w;

        if (tq == 0) {
            val.x = wa * xb[yi0 * 256 + xi0] + wb * xb[yi1 * 256 + xi0]
                  + wc * xb[yi0 * 256 + xi1] + wd * xb[yi1 * 256 + xi1];
        }

        val.x = (val.x >= 0.f) ? val.x : 0.1f * val.x;
        val.y = (val.y >= 0.f) ? val.y : 0.1f * val.y;
        val.z = (val.z >= 0.f) ? val.z : 0.1f * val.z;
        val.w = (val.w >= 0.f) ? val.w : 0.1f * val.w;

        *(float4*)(out + (((size_t)(b * 256 + oy)) * 256 + ox) * 32 + 4 * tq) = val;
    }
}

// ---------------------------------------------------------------------------
// Launch
// ---------------------------------------------------------------------------
extern "C" void kernel_launch(void* const* d_in, const int* in_sizes, int n_in,
                              void* d_out, int out_size)
{
    const float* x       = (const float*)d_in[0];
    const float* conv1_k = (const float*)d_in[1];
    const float* conv1_b = (const float*)d_in[2];
    const float* conv2_k = (const float*)d_in[3];
    const float* conv2_b = (const float*)d_in[4];
    const float* conv3_k = (const float*)d_in[5];
    const float* conv3_b = (const float*)d_in[6];
    const float* bn_gamma = (const float*)d_in[7];
    const float* bn_beta  = (const float*)d_in[8];
    const float* bn_mean  = (const float*)d_in[9];
    const float* bn_var   = (const float*)d_in[10];
    const float* d1_k = (const float*)d_in[11];
    const float* d1_b = (const float*)d_in[12];
    const float* d2_k = (const float*)d_in[13];
    const float* d2_b = (const float*)d_in[14];
    const float* d3_k = (const float*)d_in[15];
    const float* d3_b = (const float*)d_in[16];
    float* out = (float*)d_out;

    k_conv1<<<1024, 256>>>(x, conv1_k, conv1_b);
    k_conv2<<<1024, 256>>>(conv2_k, conv2_b);
    k_conv3<<<512, 256>>>(conv3_k, conv3_b);
    k_d1<<<496, 256>>>(d1_k, bn_gamma, bn_beta, bn_mean, bn_var);
    k_d1red<<<128, 256>>>(d1_b);
    k_d23<<<16, 128>>>(d2_k, d2_b, d3_k, d3_b);
    k_sampler<<<1024, 256>>>(x, out);
}

// round 10
// speedup vs baseline: 1.0545x; 1.0545x over previous
#include <cuda_runtime.h>
#include <math.h>

// ---------------------------------------------------------------------------
// Shapes
// B=16, H=W=256, C=1, LOC_C=31
// x1 (after conv1+pool): 16x128x128x8
// x2 (after conv2+pool): 16x64x64x16
// x3 (after conv3+pool): 16x32x32x31   (== x_intermediate, NHWC flatten)
// feat = 32*32*31 = 31744 = 992 * 32
// out: 16x256x256x32
// ---------------------------------------------------------------------------

#define BN_EPS 1e-3f

__device__ float g_x1[16 * 128 * 128 * 8];     // 8 MB
__device__ float g_x2[16 * 64 * 64 * 16];      // 4 MB
__device__ float g_x3[16 * 32 * 32 * 31];      // 2 MB  (packed, for d1)
__device__ float g_x3p[16 * 32 * 32 * 32];     // 2 MB  (padded+shifted, sampler)
__device__ float g_part[992 * 16 * 64];        // 4 MB  (split-K partials for d1)
__device__ float g_h1[16 * 64];                // relu(d1 output)
__device__ float g_theta[16 * 6];              // affine params

// ---- packed f32x2 helpers (Blackwell FFMA2) --------------------------------
__device__ __forceinline__ unsigned long long pk2(float a, float b) {
    unsigned long long r;
    asm("mov.b64 %0, {%1, %2};" : "=l"(r) : "f"(a), "f"(b));
    return r;
}
__device__ __forceinline__ void fma2(unsigned long long& d,
                                     unsigned long long a, unsigned long long b) {
    asm("fma.rn.f32x2 %0, %1, %2, %0;" : "+l"(d) : "l"(a), "l"(b));
}
__device__ __forceinline__ float2 upk2(unsigned long long v) {
    float2 r;
    asm("mov.b64 {%0, %1}, %2;" : "=f"(r.x), "=f"(r.y) : "l"(v));
    return r;
}

// ---------------------------------------------------------------------------
// K1: conv1 (3x3, 1->8, SAME) + ReLU + maxpool2  -> g_x1
// Block = (batch, 16x16 pooled tile). Packed f32x2 accumulation (co pairs).
// ---------------------------------------------------------------------------
__global__ __launch_bounds__(256) void k_conv1(
    const float* __restrict__ x,       // (16,256,256,1)
    const float* __restrict__ k1,      // (3,3,1,8)
    const float* __restrict__ b1)      // (8,)
{
    __shared__ float s_x[34 * 34];
    __shared__ __align__(16) float s_w[72];
    __shared__ float s_b[8];
    int tid = threadIdx.x;
    int bidx = blockIdx.x;
    int b  = bidx >> 6;
    int t  = bidx & 63;
    int ty0 = (t >> 3) * 16;
    int tx0 = (t & 7) * 16;

    if (tid < 72) s_w[tid] = k1[tid];
    if (tid < 8)  s_b[tid] = b1[tid];

    const float* xb = x + b * 65536;
    int iy0 = 2 * ty0 - 1, ix0 = 2 * tx0 - 1;
    for (int p = tid; p < 34 * 34; p += 256) {
        int r = p / 34, c = p % 34;
        int gy = iy0 + r, gx = ix0 + c;
        s_x[p] = (gy >= 0 && gy < 256 && gx >= 0 && gx < 256)
                 ? xb[gy * 256 + gx] : 0.f;
    }
    __syncthreads();

    int ly = tid >> 4, lx = tid & 15;

    float win[4][4];
#pragma unroll
    for (int r = 0; r < 4; r++)
#pragma unroll
        for (int c = 0; c < 4; c++)
            win[r][c] = s_x[(2 * ly + r) * 34 + (2 * lx + c)];

    unsigned long long acc2[4][4];     // [pos][co-pair], pair = (2co,2co+1)
#pragma unroll
    for (int p = 0; p < 4; p++)
#pragma unroll
        for (int k = 0; k < 4; k++) acc2[p][k] = 0ull;

#pragma unroll
    for (int ky = 0; ky < 3; ky++) {
#pragma unroll
        for (int kx = 0; kx < 3; kx++) {
            ulonglong2 wa = *(const ulonglong2*)&s_w[(ky * 3 + kx) * 8];
            ulonglong2 wb = *(const ulonglong2*)&s_w[(ky * 3 + kx) * 8 + 4];
#pragma unroll
            for (int dy = 0; dy < 2; dy++) {
#pragma unroll
                for (int dx = 0; dx < 2; dx++) {
                    float v = win[dy + ky][dx + kx];
                    unsigned long long vv = pk2(v, v);
                    int p = dy * 2 + dx;
                    fma2(acc2[p][0], vv, wa.x);
                    fma2(acc2[p][1], vv, wa.y);
                    fma2(acc2[p][2], vv, wb.x);
                    fma2(acc2[p][3], vv, wb.y);
                }
            }
        }
    }

    float o[8];
#pragma unroll
    for (int k = 0; k < 4; k++) {
        float2 p0 = upk2(acc2[0][k]), p1 = upk2(acc2[1][k]);
        float2 p2 = upk2(acc2[2][k]), p3 = upk2(acc2[3][k]);
        float mx = fmaxf(fmaxf(p0.x, p1.x), fmaxf(p2.x, p3.x));
        float my = fmaxf(fmaxf(p0.y, p1.y), fmaxf(p2.y, p3.y));
        o[2 * k]     = fmaxf(mx + s_b[2 * k], 0.f);
        o[2 * k + 1] = fmaxf(my + s_b[2 * k + 1], 0.f);
    }
    int py = ty0 + ly, px = tx0 + lx;
    float* op = g_x1 + ((size_t)(b * 128 + py) * 128 + px) * 8;
    *(float4*)op       = make_float4(o[0], o[1], o[2], o[3]);
    *(float4*)(op + 4) = make_float4(o[4], o[5], o[6], o[7]);
}

// ---------------------------------------------------------------------------
// K2: conv2 (3x3, 8->16) + ReLU + pool -> g_x2
// 1024 blocks: (batch, 8x8 pooled tile). Thread = (pixel, 4-co group).
// Packed f32x2: acc2[pos][pair], weight pairs via ulonglong2 LDS.
// ---------------------------------------------------------------------------
__global__ __launch_bounds__(256) void k_conv2(
    const float* __restrict__ k2,      // (3,3,8,16)
    const float* __restrict__ b2)      // (16,)
{
    __shared__ __align__(16) float s_in[18 * 18 * 8];  // 2592 floats
    __shared__ __align__(16) float s_w[1152];
    __shared__ float s_b[16];

    int tid = threadIdx.x;
    int bidx = blockIdx.x;
    int b  = bidx >> 6;
    int t  = bidx & 63;
    int ty0 = (t >> 3) * 8;
    int tx0 = (t & 7) * 8;

    for (int i = tid; i < 1152; i += 256) s_w[i] = k2[i];
    if (tid < 16) s_b[tid] = b2[tid];

    int iy0 = 2 * ty0 - 1, ix0 = 2 * tx0 - 1;
    for (int p = tid; p < 18 * 18; p += 256) {
        int r = p / 18, c = p % 18;
        int gy = iy0 + r, gx = ix0 + c;
        float* dst = &s_in[p * 8];
        if (gy >= 0 && gy < 128 && gx >= 0 && gx < 128) {
            const float* src = g_x1 + ((size_t)(b * 128 + gy) * 128 + gx) * 8;
            *(float4*)dst       = *(const float4*)src;
            *(float4*)(dst + 4) = *(const float4*)(src + 4);
        } else {
            *(float4*)dst       = make_float4(0, 0, 0, 0);
            *(float4*)(dst + 4) = make_float4(0, 0, 0, 0);
        }
    }
    __syncthreads();

    int pix = tid >> 2, cog = tid & 3, cb = cog * 4;
    int ly = pix >> 3, lx = pix & 7;

    unsigned long long acc2[4][2];     // [pos][co-pair]
#pragma unroll
    for (int p = 0; p < 4; p++) { acc2[p][0] = 0ull; acc2[p][1] = 0ull; }

#pragma unroll
    for (int ky = 0; ky < 3; ky++) {
#pragma unroll
        for (int kx = 0; kx < 3; kx++) {
            const float* wtap = &s_w[(ky * 3 + kx) * 128 + cb];
#pragma unroll
            for (int ciq = 0; ciq < 2; ciq++) {
                float iv[4][4];
#pragma unroll
                for (int dy = 0; dy < 2; dy++) {
#pragma unroll
                    for (int dx = 0; dx < 2; dx++) {
                        float4 v = *(const float4*)&s_in[
                            ((2 * ly + dy + ky) * 18 + (2 * lx + dx + kx)) * 8 + ciq * 4];
                        int p = dy * 2 + dx;
                        iv[p][0] = v.x; iv[p][1] = v.y; iv[p][2] = v.z; iv[p][3] = v.w;
                    }
                }
#pragma unroll
                for (int c = 0; c < 4; c++) {
                    ulonglong2 w2 = *(const ulonglong2*)(wtap + (ciq * 4 + c) * 16);
#pragma unroll
                    for (int p = 0; p < 4; p++) {
                        unsigned long long vv = pk2(iv[p][c], iv[p][c]);
                        fma2(acc2[p][0], vv, w2.x);
                        fma2(acc2[p][1], vv, w2.y);
                    }
                }
            }
        }
    }

    float m[4];
    {
        float2 a0 = upk2(acc2[0][0]), a1 = upk2(acc2[1][0]);
        float2 a2 = upk2(acc2[2][0]), a3 = upk2(acc2[3][0]);
        m[0] = fmaxf(fmaxf(a0.x, a1.x), fmaxf(a2.x, a3.x));
        m[1] = fmaxf(fmaxf(a0.y, a1.y), fmaxf(a2.y, a3.y));
        float2 b0 = upk2(acc2[0][1]), b1 = upk2(acc2[1][1]);
        float2 b2_ = upk2(acc2[2][1]), b3 = upk2(acc2[3][1]);
        m[2] = fmaxf(fmaxf(b0.x, b1.x), fmaxf(b2_.x, b3.x));
        m[3] = fmaxf(fmaxf(b0.y, b1.y), fmaxf(b2_.y, b3.y));
    }

    int py = ty0 + ly, px = tx0 + lx;
    float* op = g_x2 + ((size_t)(b * 64 + py) * 64 + px) * 16 + cb;
    *(float4*)op = make_float4(fmaxf(m[0] + s_b[cb], 0.f),
                               fmaxf(m[1] + s_b[cb + 1], 0.f),
                               fmaxf(m[2] + s_b[cb + 2], 0.f),
                               fmaxf(m[3] + s_b[cb + 3], 0.f));
}

// ---------------------------------------------------------------------------
// K3: conv3 (3x3, 16->31) + ReLU + pool -> g_x3 (packed) + g_x3p (padded)
// Packed f32x2 accumulation, same scheme as conv2 (co padded to 32).
// g_x3p layout: [b][cell][32] where slot c holds OUTPUT channel c
// (slot 0 = 0, slots 1..31 = conv3 channels 0..30).
// ---------------------------------------------------------------------------
__global__ __launch_bounds__(256) void k_conv3(
    const float* __restrict__ k3,      // (3,3,16,31)
    const float* __restrict__ b3)      // (31,)
{
    __shared__ __align__(16) float s_in[10 * 18 * 16];  // 2880 floats
    __shared__ __align__(16) float s_w[9 * 16 * 32];    // 4608 floats (co padded)
    __shared__ float s_b[32];

    int tid = threadIdx.x;
    int bidx = blockIdx.x;
    int b  = bidx >> 5;
    int t  = bidx & 31;
    int ty0 = (t >> 2) * 4;
    int tx0 = (t & 3) * 8;

    for (int i = tid; i < 4608; i += 256) {
        int tap = i >> 9;
        int rem = i & 511;
        int ci = rem >> 5, co = rem & 31;
        s_w[i] = (co < 31) ? k3[tap * 496 + ci * 31 + co] : 0.f;
    }
    if (tid < 32) s_b[tid] = (tid < 31) ? b3[tid] : 0.f;

    int iy0 = 2 * ty0 - 1, ix0 = 2 * tx0 - 1;
    for (int p = tid; p < 10 * 18; p += 256) {
        int r = p / 18, c = p % 18;
        int gy = iy0 + r, gx = ix0 + c;
        float* dst = &s_in[p * 16];
        if (gy >= 0 && gy < 64 && gx >= 0 && gx < 64) {
            const float* src = g_x2 + ((size_t)(b * 64 + gy) * 64 + gx) * 16;
#pragma unroll
            for (int q = 0; q < 4; q++)
                *(float4*)(dst + q * 4) = *(const float4*)(src + q * 4);
        } else {
#pragma unroll
            for (int q = 0; q < 4; q++)
                *(float4*)(dst + q * 4) = make_float4(0, 0, 0, 0);
        }
    }
    __syncthreads();

    int pix = tid >> 3, cog = tid & 7, cb = cog * 4;
    int ly = pix >> 3, lx = pix & 7;

    unsigned long long acc2[4][2];
#pragma unroll
    for (int p = 0; p < 4; p++) { acc2[p][0] = 0ull; acc2[p][1] = 0ull; }

#pragma unroll
    for (int ky = 0; ky < 3; ky++) {
#pragma unroll
        for (int kx = 0; kx < 3; kx++) {
            const float* wtap = &s_w[(ky * 3 + kx) * 512 + cb];
#pragma unroll
            for (int ciq = 0; ciq < 4; ciq++) {
                float iv[4][4];
#pragma unroll
                for (int dy = 0; dy < 2; dy++) {
#pragma unroll
                    for (int dx = 0; dx < 2; dx++) {
                        float4 v = *(const float4*)&s_in[
                            ((2 * ly + dy + ky) * 18 + (2 * lx + dx + kx)) * 16 + ciq * 4];
                        int p = dy * 2 + dx;
                        iv[p][0] = v.x; iv[p][1] = v.y; iv[p][2] = v.z; iv[p][3] = v.w;
                    }
                }
#pragma unroll
                for (int c = 0; c < 4; c++) {
                    ulonglong2 w2 = *(const ulonglong2*)(wtap + (ciq * 4 + c) * 32);
#pragma unroll
                    for (int p = 0; p < 4; p++) {
                        unsigned long long vv = pk2(iv[p][c], iv[p][c]);
                        fma2(acc2[p][0], vv, w2.x);
                        fma2(acc2[p][1], vv, w2.y);
                    }
                }
            }
        }
    }

    float m[4];
    {
        float2 a0 = upk2(acc2[0][0]), a1 = upk2(acc2[1][0]);
        float2 a2 = upk2(acc2[2][0]), a3 = upk2(acc2[3][0]);
        m[0] = fmaxf(fmaxf(a0.x, a1.x), fmaxf(a2.x, a3.x));
        m[1] = fmaxf(fmaxf(a0.y, a1.y), fmaxf(a2.y, a3.y));
        float2 b0 = upk2(acc2[0][1]), b1 = upk2(acc2[1][1]);
        float2 b2_ = upk2(acc2[2][1]), b3_ = upk2(acc2[3][1]);
        m[2] = fmaxf(fmaxf(b0.x, b1.x), fmaxf(b2_.x, b3_.x));
        m[3] = fmaxf(fmaxf(b0.y, b1.y), fmaxf(b2_.y, b3_.y));
    }

    int py = ty0 + ly, px = tx0 + lx;
    int cell = (b * 32 + py) * 32 + px;
    float* op  = g_x3  + (size_t)cell * 31;
    float* opp = g_x3p + (size_t)cell * 32;
    if (cog == 0) opp[0] = 0.f;
#pragma unroll
    for (int k = 0; k < 4; k++) {
        int co = cb + k;
        if (co < 31) {
            float v = fmaxf(m[k] + s_b[co], 0.f);
            op[co] = v;
            opp[co + 1] = v;
        }
    }
}

// ---------------------------------------------------------------------------
// K5: d1 split-K with fused BN affine. 992 blocks, 32-feature slices.
// ---------------------------------------------------------------------------
__global__ __launch_bounds__(256) void k_d1(
    const float* __restrict__ d1k,
    const float* __restrict__ gamma, const float* __restrict__ beta,
    const float* __restrict__ mean,  const float* __restrict__ var)
{
    __shared__ __align__(16) float ks[32 * 64];   // 8 KB
    __shared__ __align__(16) float gs[16 * 32];   // 2 KB
    __shared__ float s_sc[32], s_sh[32];
    int tid = threadIdx.x;
    int p = blockIdx.x;

    const float4* kbase = (const float4*)(d1k + (size_t)p * 2048);
    float4* ks4 = (float4*)ks;
    ks4[tid]       = kbase[tid];
    ks4[tid + 256] = kbase[tid + 256];

    if (tid < 32) {
        int f = p * 32 + tid;
        float sc = rsqrtf(var[f] + BN_EPS) * gamma[f];
        s_sc[tid] = sc;
        s_sh[tid] = beta[f] - mean[f] * sc;
    }
    __syncthreads();
    for (int i = tid; i < 512; i += 256) {
        int bb = i >> 5, ii = i & 31;
        gs[i] = g_x3[bb * 31744 + p * 32 + ii] * s_sc[ii] + s_sh[ii];
    }
    __syncthreads();

    int j = tid & 63, bq = tid >> 6;
    float a0 = 0.f, a1 = 0.f, a2 = 0.f, a3 = 0.f;
#pragma unroll 8
    for (int i = 0; i < 32; i++) {
        float kv = ks[i * 64 + j];
        a0 += gs[bq * 32 + i]        * kv;
        a1 += gs[(bq + 4) * 32 + i]  * kv;
        a2 += gs[(bq + 8) * 32 + i]  * kv;
        a3 += gs[(bq + 12) * 32 + i] * kv;
    }
    g_part[((size_t)p * 16 + bq)      * 64 + j] = a0;
    g_part[((size_t)p * 16 + bq + 4)  * 64 + j] = a1;
    g_part[((size_t)p * 16 + bq + 8)  * 64 + j] = a2;
    g_part[((size_t)p * 16 + bq + 12) * 64 + j] = a3;
}

// K6: reduce partials + bias + relu -> g_h1. Warp per (b,j), shuffle reduce.
__global__ __launch_bounds__(256) void k_d1red(const float* __restrict__ d1b)
{
    int gwarp = (blockIdx.x * 256 + threadIdx.x) >> 5;   // 0..1023
    int lane = threadIdx.x & 31;
    int b = gwarp >> 6, j = gwarp & 63;
    float s = 0.f;
    for (int p = lane; p < 992; p += 32)
        s += g_part[((size_t)p * 16 + b) * 64 + j];
#pragma unroll
    for (int o = 16; o; o >>= 1) s += __shfl_xor_sync(0xFFFFFFFFu, s, o);
    if (lane == 0) g_h1[b * 64 + j] = fmaxf(s + d1b[j], 0.f);
}

// K7: d2 (64->96, relu) + d3 (96->6) -> g_theta. One block per batch.
__global__ __launch_bounds__(128) void k_d23(
    const float* __restrict__ d2k, const float* __restrict__ d2b,
    const float* __restrict__ d3k, const float* __restrict__ d3b)
{
    __shared__ float h1s[64];
    __shared__ float h2s[96];
    int tid = threadIdx.x;
    int b = blockIdx.x;
    if (tid < 64) h1s[tid] = g_h1[b * 64 + tid];
    __syncthreads();
    if (tid < 96) {
        float s = d2b[tid];
#pragma unroll 8
        for (int i = 0; i < 64; i++) s += h1s[i] * d2k[i * 96 + tid];
        h2s[tid] = fmaxf(s, 0.f);
    }
    __syncthreads();
    if (tid < 6) {
        float s = d3b[tid];
#pragma unroll 8
        for (int j = 0; j < 96; j++) s += h2s[j] * d3k[j * 6 + tid];
        g_theta[b * 6 + tid] = s;
    }
}

// ---------------------------------------------------------------------------
// K8: fused grid-gen + bilinear sampler + leaky relu (R8 version)
// 4 pixels per warp, 8 lanes per pixel, lane handles channel quad 4t..4t+3.
// Uniform path: 4x LDG.128 gathers from padded g_x3p; t==0 lanes overwrite
// channel 0 with the fine-resolution bilinear sample of x.
// ---------------------------------------------------------------------------
__global__ __launch_bounds__(256) void k_sampler(
    const float* __restrict__ x,       // (16,256,256,1)
    float* __restrict__ out)           // (16,256,256,32)
{
    int gp = blockIdx.x * 32 + (threadIdx.x >> 3);   // pixel id
    int t  = threadIdx.x & 7;                        // channel quad
    int b   = gp >> 16;
    int rem = gp & 0xFFFF;
    int oy  = rem >> 8;
    int ox  = rem & 255;

    const float* th = g_theta + b * 6;
    float gx = ((float)ox / 255.f) * 2.f - 1.f;
    float gy = ((float)oy / 255.f) * 2.f - 1.f;
    float tgx = gx * th[0] + gy * th[3] + th[2];
    float tgy = gx * th[1] + gy * th[4] + th[5];

    float fx = 0.5f * ((tgx + 1.f) * 255.f);
    float fy = 0.5f * ((tgy + 1.f) * 255.f);
    float x0f = floorf(fx), x1f = x0f + 1.f;
    float y0f = floorf(fy), y1f = y0f + 1.f;
    x0f = fminf(fmaxf(x0f, 0.f), 255.f);
    x1f = fminf(fmaxf(x1f, 0.f), 255.f);
    y0f = fminf(fmaxf(y0f, 0.f), 255.f);
    y1f = fminf(fmaxf(y1f, 0.f), 255.f);
    float wa = (x1f - fx) * (y1f - fy);
    float wb = (x1f - fx) * (fy - y0f);
    float wc = (fx - x0f) * (y1f - fy);
    float wd = (fx - x0f) * (fy - y0f);
    int xi0 = (int)x0f, xi1 = (int)x1f, yi0 = (int)y0f, yi1 = (int)y1f;

    // coarse cells for the nearest-upsampled x3 (loc_up[y][x] = x3[y>>3][x>>3])
    int cy0 = yi0 >> 3, cy1 = yi1 >> 3, cx0 = xi0 >> 3, cx1 = xi1 >> 3;
    int ca  = cy0 * 32 + cx0;
    int cb_ = cy1 * 32 + cx0;
    int cc_ = cy0 * 32 + cx1;
    int cd  = cy1 * 32 + cx1;

    const float* xp = g_x3p + (size_t)b * 32768 + 4 * t;
    float4 va = *(const float4*)(xp + ca  * 32);
    float4 vb = *(const float4*)(xp + cb_ * 32);
    float4 vc = *(const float4*)(xp + cc_ * 32);
    float4 vd = *(const float4*)(xp + cd  * 32);

    float4 val;
    val.x = wa * va.x + wb * vb.x + wc * vc.x + wd * vd.x;
    val.y = wa * va.y + wb * vb.y + wc * vc.y + wd * vd.y;
    val.z = wa * va.z + wb * vb.z + wc * vc.z + wd * vd.z;
    val.w = wa * va.w + wb * vb.w + wc * vc.w + wd * vd.w;

    if (t == 0) {
        const float* xb = x + (size_t)b * 65536;
        val.x = wa * xb[yi0 * 256 + xi0] + wb * xb[yi1 * 256 + xi0]
              + wc * xb[yi0 * 256 + xi1] + wd * xb[yi1 * 256 + xi1];
    }

    val.x = (val.x >= 0.f) ? val.x : 0.1f * val.x;
    val.y = (val.y >= 0.f) ? val.y : 0.1f * val.y;
    val.z = (val.z >= 0.f) ? val.z : 0.1f * val.z;
    val.w = (val.w >= 0.f) ? val.w : 0.1f * val.w;

    *(float4*)(out + (size_t)gp * 32 + 4 * t) = val;
}

// ---------------------------------------------------------------------------
// Launch
// ---------------------------------------------------------------------------
extern "C" void kernel_launch(void* const* d_in, const int* in_sizes, int n_in,
                              void* d_out, int out_size)
{
    const float* x       = (const float*)d_in[0];
    const float* conv1_k = (const float*)d_in[1];
    const float* conv1_b = (const float*)d_in[2];
    const float* conv2_k = (const float*)d_in[3];
    const float* conv2_b = (const float*)d_in[4];
    const float* conv3_k = (const float*)d_in[5];
    const float* conv3_b = (const float*)d_in[6];
    const float* bn_gamma = (const float*)d_in[7];
    const float* bn_beta  = (const float*)d_in[8];
    const float* bn_mean  = (const float*)d_in[9];
    const float* bn_var   = (const float*)d_in[10];
    const float* d1_k = (const float*)d_in[11];
    const float* d1_b = (const float*)d_in[12];
    const float* d2_k = (const float*)d_in[13];
    const float* d2_b = (const float*)d_in[14];
    const float* d3_k = (const float*)d_in[15];
    const float* d3_b = (const float*)d_in[16];
    float* out = (float*)d_out;

    k_conv1<<<1024, 256>>>(x, conv1_k, conv1_b);
    k_conv2<<<1024, 256>>>(conv2_k, conv2_b);
    k_conv3<<<512, 256>>>(conv3_k, conv3_b);
    k_d1<<<992, 256>>>(d1_k, bn_gamma, bn_beta, bn_mean, bn_var);
    k_d1red<<<128, 256>>>(d1_b);
    k_d23<<<16, 128>>>(d2_k, d2_b, d3_k, d3_b);
    k_sampler<<<32768, 256>>>(x, out);
}

// round 11
// speedup vs baseline: 1.0548x; 1.0003x over previous
#include <cuda_runtime.h>
#include <math.h>

// ---------------------------------------------------------------------------
// Shapes
// B=16, H=W=256, C=1, LOC_C=31
// x1 (after conv1+pool): 16x128x128x8
// x2 (after conv2+pool): 16x64x64x16
// x3 (after conv3+pool): 16x32x32x31   (== x_intermediate, NHWC flatten)
// feat = 32*32*31 = 31744 = 992 * 32
// out: 16x256x256x32
// ---------------------------------------------------------------------------

#define BN_EPS 1e-3f

__device__ float g_x1[16 * 128 * 128 * 8];     // 8 MB
__device__ float g_x2[16 * 64 * 64 * 16];      // 4 MB
__device__ float g_x3[16 * 32 * 32 * 31];      // 2 MB  (packed, for d1)
__device__ float g_x3p[16 * 32 * 32 * 32];     // 2 MB  (padded+shifted, sampler)
__device__ float g_part[992 * 16 * 64];        // 4 MB  (split-K partials for d1)
__device__ float g_h1[16 * 64];                // relu(d1 output)
__device__ float g_theta[16 * 6];              // affine params

// ---- packed f32x2 helpers (Blackwell FFMA2) --------------------------------
__device__ __forceinline__ unsigned long long pk2(float a, float b) {
    unsigned long long r;
    asm("mov.b64 %0, {%1, %2};" : "=l"(r) : "f"(a), "f"(b));
    return r;
}
__device__ __forceinline__ void fma2(unsigned long long& d,
                                     unsigned long long a, unsigned long long b) {
    asm("fma.rn.f32x2 %0, %1, %2, %0;" : "+l"(d) : "l"(a), "l"(b));
}
__device__ __forceinline__ float2 upk2(unsigned long long v) {
    float2 r;
    asm("mov.b64 {%0, %1}, %2;" : "=f"(r.x), "=f"(r.y) : "l"(v));
    return r;
}

// ---------------------------------------------------------------------------
// K1: conv1 (3x3, 1->8, SAME) + ReLU + maxpool2  -> g_x1
// Block = (batch, 16x16 pooled tile). Packed f32x2 accumulation (co pairs).
// ---------------------------------------------------------------------------
__global__ __launch_bounds__(256) void k_conv1(
    const float* __restrict__ x,       // (16,256,256,1)
    const float* __restrict__ k1,      // (3,3,1,8)
    const float* __restrict__ b1)      // (8,)
{
    __shared__ float s_x[34 * 34];
    __shared__ __align__(16) float s_w[72];
    __shared__ float s_b[8];
    int tid = threadIdx.x;
    int bidx = blockIdx.x;
    int b  = bidx >> 6;
    int t  = bidx & 63;
    int ty0 = (t >> 3) * 16;
    int tx0 = (t & 7) * 16;

    if (tid < 72) s_w[tid] = k1[tid];
    if (tid < 8)  s_b[tid] = b1[tid];

    const float* xb = x + b * 65536;
    int iy0 = 2 * ty0 - 1, ix0 = 2 * tx0 - 1;
    for (int p = tid; p < 34 * 34; p += 256) {
        int r = p / 34, c = p % 34;
        int gy = iy0 + r, gx = ix0 + c;
        s_x[p] = (gy >= 0 && gy < 256 && gx >= 0 && gx < 256)
                 ? xb[gy * 256 + gx] : 0.f;
    }
    __syncthreads();

    int ly = tid >> 4, lx = tid & 15;

    float win[4][4];
#pragma unroll
    for (int r = 0; r < 4; r++)
#pragma unroll
        for (int c = 0; c < 4; c++)
            win[r][c] = s_x[(2 * ly + r) * 34 + (2 * lx + c)];

    unsigned long long acc2[4][4];     // [pos][co-pair], pair = (2co,2co+1)
#pragma unroll
    for (int p = 0; p < 4; p++)
#pragma unroll
        for (int k = 0; k < 4; k++) acc2[p][k] = 0ull;

#pragma unroll
    for (int ky = 0; ky < 3; ky++) {
#pragma unroll
        for (int kx = 0; kx < 3; kx++) {
            ulonglong2 wa = *(const ulonglong2*)&s_w[(ky * 3 + kx) * 8];
            ulonglong2 wb = *(const ulonglong2*)&s_w[(ky * 3 + kx) * 8 + 4];
#pragma unroll
            for (int dy = 0; dy < 2; dy++) {
#pragma unroll
                for (int dx = 0; dx < 2; dx++) {
                    float v = win[dy + ky][dx + kx];
                    unsigned long long vv = pk2(v, v);
                    int p = dy * 2 + dx;
                    fma2(acc2[p][0], vv, wa.x);
                    fma2(acc2[p][1], vv, wa.y);
                    fma2(acc2[p][2], vv, wb.x);
                    fma2(acc2[p][3], vv, wb.y);
                }
            }
        }
    }

    float o[8];
#pragma unroll
    for (int k = 0; k < 4; k++) {
        float2 p0 = upk2(acc2[0][k]), p1 = upk2(acc2[1][k]);
        float2 p2 = upk2(acc2[2][k]), p3 = upk2(acc2[3][k]);
        float mx = fmaxf(fmaxf(p0.x, p1.x), fmaxf(p2.x, p3.x));
        float my = fmaxf(fmaxf(p0.y, p1.y), fmaxf(p2.y, p3.y));
        o[2 * k]     = fmaxf(mx + s_b[2 * k], 0.f);
        o[2 * k + 1] = fmaxf(my + s_b[2 * k + 1], 0.f);
    }
    int py = ty0 + ly, px = tx0 + lx;
    float* op = g_x1 + ((size_t)(b * 128 + py) * 128 + px) * 8;
    *(float4*)op       = make_float4(o[0], o[1], o[2], o[3]);
    *(float4*)(op + 4) = make_float4(o[4], o[5], o[6], o[7]);
}

// ---------------------------------------------------------------------------
// K2: conv2 (3x3, 8->16) + ReLU + pool -> g_x2
// 1024 blocks: (batch, 8x8 pooled tile). Thread = (pixel, 4-co group).
// Packed f32x2: acc2[pos][pair], weight pairs via ulonglong2 LDS.
// ---------------------------------------------------------------------------
__global__ __launch_bounds__(256) void k_conv2(
    const float* __restrict__ k2,      // (3,3,8,16)
    const float* __restrict__ b2)      // (16,)
{
    __shared__ __align__(16) float s_in[18 * 18 * 8];  // 2592 floats
    __shared__ __align__(16) float s_w[1152];
    __shared__ float s_b[16];

    int tid = threadIdx.x;
    int bidx = blockIdx.x;
    int b  = bidx >> 6;
    int t  = bidx & 63;
    int ty0 = (t >> 3) * 8;
    int tx0 = (t & 7) * 8;

    for (int i = tid; i < 1152; i += 256) s_w[i] = k2[i];
    if (tid < 16) s_b[tid] = b2[tid];

    int iy0 = 2 * ty0 - 1, ix0 = 2 * tx0 - 1;
    for (int p = tid; p < 18 * 18; p += 256) {
        int r = p / 18, c = p % 18;
        int gy = iy0 + r, gx = ix0 + c;
        float* dst = &s_in[p * 8];
        if (gy >= 0 && gy < 128 && gx >= 0 && gx < 128) {
            const float* src = g_x1 + ((size_t)(b * 128 + gy) * 128 + gx) * 8;
            *(float4*)dst       = *(const float4*)src;
            *(float4*)(dst + 4) = *(const float4*)(src + 4);
        } else {
            *(float4*)dst       = make_float4(0, 0, 0, 0);
            *(float4*)(dst + 4) = make_float4(0, 0, 0, 0);
        }
    }
    __syncthreads();

    int pix = tid >> 2, cog = tid & 3, cb = cog * 4;
    int ly = pix >> 3, lx = pix & 7;

    unsigned long long acc2[4][2];     // [pos][co-pair]
#pragma unroll
    for (int p = 0; p < 4; p++) { acc2[p][0] = 0ull; acc2[p][1] = 0ull; }

#pragma unroll
    for (int ky = 0; ky < 3; ky++) {
#pragma unroll
        for (int kx = 0; kx < 3; kx++) {
            const float* wtap = &s_w[(ky * 3 + kx) * 128 + cb];
#pragma unroll
            for (int ciq = 0; ciq < 2; ciq++) {
                float iv[4][4];
#pragma unroll
                for (int dy = 0; dy < 2; dy++) {
#pragma unroll
                    for (int dx = 0; dx < 2; dx++) {
                        float4 v = *(const float4*)&s_in[
                            ((2 * ly + dy + ky) * 18 + (2 * lx + dx + kx)) * 8 + ciq * 4];
                        int p = dy * 2 + dx;
                        iv[p][0] = v.x; iv[p][1] = v.y; iv[p][2] = v.z; iv[p][3] = v.w;
                    }
                }
#pragma unroll
                for (int c = 0; c < 4; c++) {
                    ulonglong2 w2 = *(const ulonglong2*)(wtap + (ciq * 4 + c) * 16);
#pragma unroll
                    for (int p = 0; p < 4; p++) {
                        unsigned long long vv = pk2(iv[p][c], iv[p][c]);
                        fma2(acc2[p][0], vv, w2.x);
                        fma2(acc2[p][1], vv, w2.y);
                    }
                }
            }
        }
    }

    float m[4];
    {
        float2 a0 = upk2(acc2[0][0]), a1 = upk2(acc2[1][0]);
        float2 a2 = upk2(acc2[2][0]), a3 = upk2(acc2[3][0]);
        m[0] = fmaxf(fmaxf(a0.x, a1.x), fmaxf(a2.x, a3.x));
        m[1] = fmaxf(fmaxf(a0.y, a1.y), fmaxf(a2.y, a3.y));
        float2 b0 = upk2(acc2[0][1]), b1 = upk2(acc2[1][1]);
        float2 b2_ = upk2(acc2[2][1]), b3 = upk2(acc2[3][1]);
        m[2] = fmaxf(fmaxf(b0.x, b1.x), fmaxf(b2_.x, b3.x));
        m[3] = fmaxf(fmaxf(b0.y, b1.y), fmaxf(b2_.y, b3.y));
    }

    int py = ty0 + ly, px = tx0 + lx;
    float* op = g_x2 + ((size_t)(b * 64 + py) * 64 + px) * 16 + cb;
    *(float4*)op = make_float4(fmaxf(m[0] + s_b[cb], 0.f),
                               fmaxf(m[1] + s_b[cb + 1], 0.f),
                               fmaxf(m[2] + s_b[cb + 2], 0.f),
                               fmaxf(m[3] + s_b[cb + 3], 0.f));
}

// ---------------------------------------------------------------------------
// K3: conv3 (3x3, 16->31) + ReLU + pool -> g_x3 (packed) + g_x3p (padded)
// Packed f32x2 accumulation, same scheme as conv2 (co padded to 32).
// g_x3p layout: [b][cell][32] where slot c holds OUTPUT channel c
// (slot 0 = 0, slots 1..31 = conv3 channels 0..30).
// ---------------------------------------------------------------------------
__global__ __launch_bounds__(256) void k_conv3(
    const float* __restrict__ k3,      // (3,3,16,31)
    const float* __restrict__ b3)      // (31,)
{
    __shared__ __align__(16) float s_in[10 * 18 * 16];  // 2880 floats
    __shared__ __align__(16) float s_w[9 * 16 * 32];    // 4608 floats (co padded)
    __shared__ float s_b[32];

    int tid = threadIdx.x;
    int bidx = blockIdx.x;
    int b  = bidx >> 5;
    int t  = bidx & 31;
    int ty0 = (t >> 2) * 4;
    int tx0 = (t & 3) * 8;

    for (int i = tid; i < 4608; i += 256) {
        int tap = i >> 9;
        int rem = i & 511;
        int ci = rem >> 5, co = rem & 31;
        s_w[i] = (co < 31) ? k3[tap * 496 + ci * 31 + co] : 0.f;
    }
    if (tid < 32) s_b[tid] = (tid < 31) ? b3[tid] : 0.f;

    int iy0 = 2 * ty0 - 1, ix0 = 2 * tx0 - 1;
    for (int p = tid; p < 10 * 18; p += 256) {
        int r = p / 18, c = p % 18;
        int gy = iy0 + r, gx = ix0 + c;
        float* dst = &s_in[p * 16];
        if (gy >= 0 && gy < 64 && gx >= 0 && gx < 64) {
            const float* src = g_x2 + ((size_t)(b * 64 + gy) * 64 + gx) * 16;
#pragma unroll
            for (int q = 0; q < 4; q++)
                *(float4*)(dst + q * 4) = *(const float4*)(src + q * 4);
        } else {
#pragma unroll
            for (int q = 0; q < 4; q++)
                *(float4*)(dst + q * 4) = make_float4(0, 0, 0, 0);
        }
    }
    __syncthreads();

    int pix = tid >> 3, cog = tid & 7, cb = cog * 4;
    int ly = pix >> 3, lx = pix & 7;

    unsigned long long acc2[4][2];
#pragma unroll
    for (int p = 0; p < 4; p++) { acc2[p][0] = 0ull; acc2[p][1] = 0ull; }

#pragma unroll
    for (int ky = 0; ky < 3; ky++) {
#pragma unroll
        for (int kx = 0; kx < 3; kx++) {
            const float* wtap = &s_w[(ky * 3 + kx) * 512 + cb];
#pragma unroll
            for (int ciq = 0; ciq < 4; ciq++) {
                float iv[4][4];
#pragma unroll
                for (int dy = 0; dy < 2; dy++) {
#pragma unroll
                    for (int dx = 0; dx < 2; dx++) {
                        float4 v = *(const float4*)&s_in[
                            ((2 * ly + dy + ky) * 18 + (2 * lx + dx + kx)) * 16 + ciq * 4];
                        int p = dy * 2 + dx;
                        iv[p][0] = v.x; iv[p][1] = v.y; iv[p][2] = v.z; iv[p][3] = v.w;
                    }
                }
#pragma unroll
                for (int c = 0; c < 4; c++) {
                    ulonglong2 w2 = *(const ulonglong2*)(wtap + (ciq * 4 + c) * 32);
#pragma unroll
                    for (int p = 0; p < 4; p++) {
                        unsigned long long vv = pk2(iv[p][c], iv[p][c]);
                        fma2(acc2[p][0], vv, w2.x);
                        fma2(acc2[p][1], vv, w2.y);
                    }
                }
            }
        }
    }

    float m[4];
    {
        float2 a0 = upk2(acc2[0][0]), a1 = upk2(acc2[1][0]);
        float2 a2 = upk2(acc2[2][0]), a3 = upk2(acc2[3][0]);
        m[0] = fmaxf(fmaxf(a0.x, a1.x), fmaxf(a2.x, a3.x));
        m[1] = fmaxf(fmaxf(a0.y, a1.y), fmaxf(a2.y, a3.y));
        float2 b0 = upk2(acc2[0][1]), b1 = upk2(acc2[1][1]);
        float2 b2_ = upk2(acc2[2][1]), b3_ = upk2(acc2[3][1]);
        m[2] = fmaxf(fmaxf(b0.x, b1.x), fmaxf(b2_.x, b3_.x));
        m[3] = fmaxf(fmaxf(b0.y, b1.y), fmaxf(b2_.y, b3_.y));
    }

    int py = ty0 + ly, px = tx0 + lx;
    int cell = (b * 32 + py) * 32 + px;
    float* op  = g_x3  + (size_t)cell * 31;
    float* opp = g_x3p + (size_t)cell * 32;
    if (cog == 0) opp[0] = 0.f;
#pragma unroll
    for (int k = 0; k < 4; k++) {
        int co = cb + k;
        if (co < 31) {
            float v = fmaxf(m[k] + s_b[co], 0.f);
            op[co] = v;
            opp[co + 1] = v;
        }
    }
}

// ---------------------------------------------------------------------------
// K5: d1 split-K with fused BN affine. 992 blocks, 32-feature slices.
// ---------------------------------------------------------------------------
__global__ __launch_bounds__(256) void k_d1(
    const float* __restrict__ d1k,
    const float* __restrict__ gamma, const float* __restrict__ beta,
    const float* __restrict__ mean,  const float* __restrict__ var)
{
    __shared__ __align__(16) float ks[32 * 64];   // 8 KB
    __shared__ __align__(16) float gs[16 * 32];   // 2 KB
    __shared__ float s_sc[32], s_sh[32];
    int tid = threadIdx.x;
    int p = blockIdx.x;

    const float4* kbase = (const float4*)(d1k + (size_t)p * 2048);
    float4* ks4 = (float4*)ks;
    ks4[tid]       = kbase[tid];
    ks4[tid + 256] = kbase[tid + 256];

    if (tid < 32) {
        int f = p * 32 + tid;
        float sc = rsqrtf(var[f] + BN_EPS) * gamma[f];
        s_sc[tid] = sc;
        s_sh[tid] = beta[f] - mean[f] * sc;
    }
    __syncthreads();
    for (int i = tid; i < 512; i += 256) {
        int bb = i >> 5, ii = i & 31;
        gs[i] = g_x3[bb * 31744 + p * 32 + ii] * s_sc[ii] + s_sh[ii];
    }
    __syncthreads();

    int j = tid & 63, bq = tid >> 6;
    float a0 = 0.f, a1 = 0.f, a2 = 0.f, a3 = 0.f;
#pragma unroll 8
    for (int i = 0; i < 32; i++) {
        float kv = ks[i * 64 + j];
        a0 += gs[bq * 32 + i]        * kv;
        a1 += gs[(bq + 4) * 32 + i]  * kv;
        a2 += gs[(bq + 8) * 32 + i]  * kv;
        a3 += gs[(bq + 12) * 32 + i] * kv;
    }
    g_part[((size_t)p * 16 + bq)      * 64 + j] = a0;
    g_part[((size_t)p * 16 + bq + 4)  * 64 + j] = a1;
    g_part[((size_t)p * 16 + bq + 8)  * 64 + j] = a2;
    g_part[((size_t)p * 16 + bq + 12) * 64 + j] = a3;
}

// K6: reduce partials + bias + relu -> g_h1. Warp per (b,j), shuffle reduce.
__global__ __launch_bounds__(256) void k_d1red(const float* __restrict__ d1b)
{
    int gwarp = (blockIdx.x * 256 + threadIdx.x) >> 5;   // 0..1023
    int lane = threadIdx.x & 31;
    int b = gwarp >> 6, j = gwarp & 63;
    float s = 0.f;
    for (int p = lane; p < 992; p += 32)
        s += g_part[((size_t)p * 16 + b) * 64 + j];
#pragma unroll
    for (int o = 16; o; o >>= 1) s += __shfl_xor_sync(0xFFFFFFFFu, s, o);
    if (lane == 0) g_h1[b * 64 + j] = fmaxf(s + d1b[j], 0.f);
}

// K7: d2 (64->96, relu) + d3 (96->6) -> g_theta. One block per batch.
__global__ __launch_bounds__(128) void k_d23(
    const float* __restrict__ d2k, const float* __restrict__ d2b,
    const float* __restrict__ d3k, const float* __restrict__ d3b)
{
    __shared__ float h1s[64];
    __shared__ float h2s[96];
    int tid = threadIdx.x;
    int b = blockIdx.x;
    if (tid < 64) h1s[tid] = g_h1[b * 64 + tid];
    __syncthreads();
    if (tid < 96) {
        float s = d2b[tid];
#pragma unroll 8
        for (int i = 0; i < 64; i++) s += h1s[i] * d2k[i * 96 + tid];
        h2s[tid] = fmaxf(s, 0.f);
    }
    __syncthreads();
    if (tid < 6) {
        float s = d3b[tid];
#pragma unroll 8
        for (int j = 0; j < 96; j++) s += h2s[j] * d3k[j * 6 + tid];
        g_theta[b * 6 + tid] = s;
    }
}

// ---------------------------------------------------------------------------
// K8: fused grid-gen + bilinear sampler + leaky relu (R8 version)
// 4 pixels per warp, 8 lanes per pixel, lane handles channel quad 4t..4t+3.
// Uniform path: 4x LDG.128 gathers from padded g_x3p; t==0 lanes overwrite
// channel 0 with the fine-resolution bilinear sample of x.
// ---------------------------------------------------------------------------
__global__ __launch_bounds__(256) void k_sampler(
    const float* __restrict__ x,       // (16,256,256,1)
    float* __restrict__ out)           // (16,256,256,32)
{
    int gp = blockIdx.x * 32 + (threadIdx.x >> 3);   // pixel id
    int t  = threadIdx.x & 7;                        // channel quad
    int b   = gp >> 16;
    int rem = gp & 0xFFFF;
    int oy  = rem >> 8;
    int ox  = rem & 255;

    const float* th = g_theta + b * 6;
    float gx = ((float)ox / 255.f) * 2.f - 1.f;
    float gy = ((float)oy / 255.f) * 2.f - 1.f;
    float tgx = gx * th[0] + gy * th[3] + th[2];
    float tgy = gx * th[1] + gy * th[4] + th[5];

    float fx = 0.5f * ((tgx + 1.f) * 255.f);
    float fy = 0.5f * ((tgy + 1.f) * 255.f);
    float x0f = floorf(fx), x1f = x0f + 1.f;
    float y0f = floorf(fy), y1f = y0f + 1.f;
    x0f = fminf(fmaxf(x0f, 0.f), 255.f);
    x1f = fminf(fmaxf(x1f, 0.f), 255.f);
    y0f = fminf(fmaxf(y0f, 0.f), 255.f);
    y1f = fminf(fmaxf(y1f, 0.f), 255.f);
    float wa = (x1f - fx) * (y1f - fy);
    float wb = (x1f - fx) * (fy - y0f);
    float wc = (fx - x0f) * (y1f - fy);
    float wd = (fx - x0f) * (fy - y0f);
    int xi0 = (int)x0f, xi1 = (int)x1f, yi0 = (int)y0f, yi1 = (int)y1f;

    // coarse cells for the nearest-upsampled x3 (loc_up[y][x] = x3[y>>3][x>>3])
    int cy0 = yi0 >> 3, cy1 = yi1 >> 3, cx0 = xi0 >> 3, cx1 = xi1 >> 3;
    int ca  = cy0 * 32 + cx0;
    int cb_ = cy1 * 32 + cx0;
    int cc_ = cy0 * 32 + cx1;
    int cd  = cy1 * 32 + cx1;

    const float* xp = g_x3p + (size_t)b * 32768 + 4 * t;
    float4 va = *(const float4*)(xp + ca  * 32);
    float4 vb = *(const float4*)(xp + cb_ * 32);
    float4 vc = *(const float4*)(xp + cc_ * 32);
    float4 vd = *(const float4*)(xp + cd  * 32);

    float4 val;
    val.x = wa * va.x + wb * vb.x + wc * vc.x + wd * vd.x;
    val.y = wa * va.y + wb * vb.y + wc * vc.y + wd * vd.y;
    val.z = wa * va.z + wb * vb.z + wc * vc.z + wd * vd.z;
    val.w = wa * va.w + wb * vb.w + wc * vc.w + wd * vd.w;

    if (t == 0) {
        const float* xb = x + (size_t)b * 65536;
        val.x = wa * xb[yi0 * 256 + xi0] + wb * xb[yi1 * 256 + xi0]
              + wc * xb[yi0 * 256 + xi1] + wd * xb[yi1 * 256 + xi1];
    }

    val.x = (val.x >= 0.f) ? val.x : 0.1f * val.x;
    val.y = (val.y >= 0.f) ? val.y : 0.1f * val.y;
    val.z = (val.z >= 0.f) ? val.z : 0.1f * val.z;
    val.w = (val.w >= 0.f) ? val.w : 0.1f * val.w;

    *(float4*)(out + (size_t)gp * 32 + 4 * t) = val;
}

// ---------------------------------------------------------------------------
// Launch
// ---------------------------------------------------------------------------
extern "C" void kernel_launch(void* const* d_in, const int* in_sizes, int n_in,
                              void* d_out, int out_size)
{
    const float* x       = (const float*)d_in[0];
    const float* conv1_k = (const float*)d_in[1];
    const float* conv1_b = (const float*)d_in[2];
    const float* conv2_k = (const float*)d_in[3];
    const float* conv2_b = (const float*)d_in[4];
    const float* conv3_k = (const float*)d_in[5];
    const float* conv3_b = (const float*)d_in[6];
    const float* bn_gamma = (const float*)d_in[7];
    const float* bn_beta  = (const float*)d_in[8];
    const float* bn_mean  = (const float*)d_in[9];
    const float* bn_var   = (const float*)d_in[10];
    const float* d1_k = (const float*)d_in[11];
    const float* d1_b = (const float*)d_in[12];
    const float* d2_k = (const float*)d_in[13];
    const float* d2_b = (const float*)d_in[14];
    const float* d3_k = (const float*)d_in[15];
    const float* d3_b = (const float*)d_in[16];
    float* out = (float*)d_out;

    k_conv1<<<1024, 256>>>(x, conv1_k, conv1_b);
    k_conv2<<<1024, 256>>>(conv2_k, conv2_b);
    k_conv3<<<512, 256>>>(conv3_k, conv3_b);
    k_d1<<<992, 256>>>(d1_k, bn_gamma, bn_beta, bn_mean, bn_var);
    k_d1red<<<128, 256>>>(d1_b);
    k_d23<<<16, 128>>>(d2_k, d2_b, d3_k, d3_b);
    k_sampler<<<32768, 256>>>(x, out);
}

// round 12
// speedup vs baseline: 1.1248x; 1.0663x over previous
#include <cuda_runtime.h>
#include <math.h>

// ---------------------------------------------------------------------------
// Shapes
// B=16, H=W=256, C=1, LOC_C=31
// x1: 16x128x128x8   x2: 16x64x64x16   x3: 16x32x32x31
// feat = 31744 = 992*32 ; out: 16x256x256x32
// ---------------------------------------------------------------------------

#define BN_EPS 1e-3f

__device__ float g_x1[16 * 128 * 128 * 8];     // 8 MB
__device__ float g_x2[16 * 64 * 64 * 16];      // 4 MB
__device__ float g_x3[16 * 32 * 32 * 31];      // 2 MB  (packed, for d1)
__device__ float g_x3p[16 * 32 * 32 * 32];     // 2 MB  (padded+shifted, sampler)
__device__ float g_part[992 * 16 * 64];        // 4 MB  (split-K partials for d1)
__device__ float g_theta[16 * 6];              // affine params

// ---- packed f32x2 helpers (Blackwell FFMA2) --------------------------------
__device__ __forceinline__ unsigned long long pk2(float a, float b) {
    unsigned long long r;
    asm("mov.b64 %0, {%1, %2};" : "=l"(r) : "f"(a), "f"(b));
    return r;
}
__device__ __forceinline__ void fma2(unsigned long long& d,
                                     unsigned long long a, unsigned long long b) {
    asm("fma.rn.f32x2 %0, %1, %2, %0;" : "+l"(d) : "l"(a), "l"(b));
}
__device__ __forceinline__ float2 upk2(unsigned long long v) {
    float2 r;
    asm("mov.b64 {%0, %1}, %2;" : "=f"(r.x), "=f"(r.y) : "l"(v));
    return r;
}

// ---------------------------------------------------------------------------
// K1: conv1 (3x3, 1->8, SAME) + ReLU + maxpool2  -> g_x1
// Block = (batch, 16x16 pooled tile). Packed f32x2 accumulation (co pairs).
// ---------------------------------------------------------------------------
__global__ __launch_bounds__(256) void k_conv1(
    const float* __restrict__ x,
    const float* __restrict__ k1,
    const float* __restrict__ b1)
{
    __shared__ float s_x[34 * 34];
    __shared__ __align__(16) float s_w[72];
    __shared__ float s_b[8];
    int tid = threadIdx.x;
    int bidx = blockIdx.x;
    int b  = bidx >> 6;
    int t  = bidx & 63;
    int ty0 = (t >> 3) * 16;
    int tx0 = (t & 7) * 16;

    if (tid < 72) s_w[tid] = k1[tid];
    if (tid < 8)  s_b[tid] = b1[tid];

    const float* xb = x + b * 65536;
    int iy0 = 2 * ty0 - 1, ix0 = 2 * tx0 - 1;
    for (int p = tid; p < 34 * 34; p += 256) {
        int r = p / 34, c = p % 34;
        int gy = iy0 + r, gx = ix0 + c;
        s_x[p] = (gy >= 0 && gy < 256 && gx >= 0 && gx < 256)
                 ? xb[gy * 256 + gx] : 0.f;
    }
    __syncthreads();

    int ly = tid >> 4, lx = tid & 15;

    float win[4][4];
#pragma unroll
    for (int r = 0; r < 4; r++)
#pragma unroll
        for (int c = 0; c < 4; c++)
            win[r][c] = s_x[(2 * ly + r) * 34 + (2 * lx + c)];

    unsigned long long acc2[4][4];
#pragma unroll
    for (int p = 0; p < 4; p++)
#pragma unroll
        for (int k = 0; k < 4; k++) acc2[p][k] = 0ull;

#pragma unroll
    for (int ky = 0; ky < 3; ky++) {
#pragma unroll
        for (int kx = 0; kx < 3; kx++) {
            ulonglong2 wa = *(const ulonglong2*)&s_w[(ky * 3 + kx) * 8];
            ulonglong2 wb = *(const ulonglong2*)&s_w[(ky * 3 + kx) * 8 + 4];
#pragma unroll
            for (int dy = 0; dy < 2; dy++) {
#pragma unroll
                for (int dx = 0; dx < 2; dx++) {
                    float v = win[dy + ky][dx + kx];
                    unsigned long long vv = pk2(v, v);
                    int p = dy * 2 + dx;
                    fma2(acc2[p][0], vv, wa.x);
                    fma2(acc2[p][1], vv, wa.y);
                    fma2(acc2[p][2], vv, wb.x);
                    fma2(acc2[p][3], vv, wb.y);
                }
            }
        }
    }

    float o[8];
#pragma unroll
    for (int k = 0; k < 4; k++) {
        float2 p0 = upk2(acc2[0][k]), p1 = upk2(acc2[1][k]);
        float2 p2 = upk2(acc2[2][k]), p3 = upk2(acc2[3][k]);
        float mx = fmaxf(fmaxf(p0.x, p1.x), fmaxf(p2.x, p3.x));
        float my = fmaxf(fmaxf(p0.y, p1.y), fmaxf(p2.y, p3.y));
        o[2 * k]     = fmaxf(mx + s_b[2 * k], 0.f);
        o[2 * k + 1] = fmaxf(my + s_b[2 * k + 1], 0.f);
    }
    int py = ty0 + ly, px = tx0 + lx;
    float* op = g_x1 + ((size_t)(b * 128 + py) * 128 + px) * 8;
    *(float4*)op       = make_float4(o[0], o[1], o[2], o[3]);
    *(float4*)(op + 4) = make_float4(o[4], o[5], o[6], o[7]);
}

// ---------------------------------------------------------------------------
// K2: conv2 (3x3, 8->16) + ReLU + pool -> g_x2
// 512 blocks: (batch, 8x16 pooled tile). Thread = (pixel, 8-co group).
// ---------------------------------------------------------------------------
__global__ __launch_bounds__(256) void k_conv2(
    const float* __restrict__ k2,      // (3,3,8,16)
    const float* __restrict__ b2)      // (16,)
{
    __shared__ __align__(16) float s_in[18 * 34 * 8];  // 4896 floats
    __shared__ __align__(16) float s_w[1152];
    __shared__ float s_b[16];

    int tid = threadIdx.x;
    int bidx = blockIdx.x;
    int b  = bidx >> 5;
    int t  = bidx & 31;                 // 8 ty-tiles x 4 tx-tiles
    int ty0 = (t >> 2) * 8;
    int tx0 = (t & 3) * 16;

    for (int i = tid; i < 1152; i += 256) s_w[i] = k2[i];
    if (tid < 16) s_b[tid] = b2[tid];

    int iy0 = 2 * ty0 - 1, ix0 = 2 * tx0 - 1;
    for (int p = tid; p < 18 * 34; p += 256) {
        int r = p / 34, c = p % 34;
        int gy = iy0 + r, gx = ix0 + c;
        float* dst = &s_in[p * 8];
        if (gy >= 0 && gy < 128 && gx >= 0 && gx < 128) {
            const float* src = g_x1 + ((size_t)(b * 128 + gy) * 128 + gx) * 8;
            *(float4*)dst       = *(const float4*)src;
            *(float4*)(dst + 4) = *(const float4*)(src + 4);
        } else {
            *(float4*)dst       = make_float4(0, 0, 0, 0);
            *(float4*)(dst + 4) = make_float4(0, 0, 0, 0);
        }
    }
    __syncthreads();

    int pix = tid >> 1, cog = tid & 1, cb = cog * 8;
    int ly = pix >> 4, lx = pix & 15;

    unsigned long long acc2[4][4];     // [pos][co-pair of 8]
#pragma unroll
    for (int p = 0; p < 4; p++)
#pragma unroll
        for (int k = 0; k < 4; k++) acc2[p][k] = 0ull;

#pragma unroll
    for (int ky = 0; ky < 3; ky++) {
#pragma unroll
        for (int kx = 0; kx < 3; kx++) {
            const float* wtap = &s_w[(ky * 3 + kx) * 128 + cb];
#pragma unroll
            for (int ciq = 0; ciq < 2; ciq++) {
                float iv[4][4];
#pragma unroll
                for (int dy = 0; dy < 2; dy++) {
#pragma unroll
                    for (int dx = 0; dx < 2; dx++) {
                        float4 v = *(const float4*)&s_in[
                            ((2 * ly + dy + ky) * 34 + (2 * lx + dx + kx)) * 8 + ciq * 4];
                        int p = dy * 2 + dx;
                        iv[p][0] = v.x; iv[p][1] = v.y; iv[p][2] = v.z; iv[p][3] = v.w;
                    }
                }
#pragma unroll
                for (int c = 0; c < 4; c++) {
                    ulonglong2 w0 = *(const ulonglong2*)(wtap + (ciq * 4 + c) * 16);
                    ulonglong2 w1 = *(const ulonglong2*)(wtap + (ciq * 4 + c) * 16 + 4);
#pragma unroll
                    for (int p = 0; p < 4; p++) {
                        unsigned long long vv = pk2(iv[p][c], iv[p][c]);
                        fma2(acc2[p][0], vv, w0.x);
                        fma2(acc2[p][1], vv, w0.y);
                        fma2(acc2[p][2], vv, w1.x);
                        fma2(acc2[p][3], vv, w1.y);
                    }
                }
            }
        }
    }

    float o[8];
#pragma unroll
    for (int k = 0; k < 4; k++) {
        float2 p0 = upk2(acc2[0][k]), p1 = upk2(acc2[1][k]);
        float2 p2 = upk2(acc2[2][k]), p3 = upk2(acc2[3][k]);
        float mx = fmaxf(fmaxf(p0.x, p1.x), fmaxf(p2.x, p3.x));
        float my = fmaxf(fmaxf(p0.y, p1.y), fmaxf(p2.y, p3.y));
        o[2 * k]     = fmaxf(mx + s_b[cb + 2 * k], 0.f);
        o[2 * k + 1] = fmaxf(my + s_b[cb + 2 * k + 1], 0.f);
    }

    int py = ty0 + ly, px = tx0 + lx;
    float* op = g_x2 + ((size_t)(b * 64 + py) * 64 + px) * 16 + cb;
    *(float4*)op       = make_float4(o[0], o[1], o[2], o[3]);
    *(float4*)(op + 4) = make_float4(o[4], o[5], o[6], o[7]);
}

// ---------------------------------------------------------------------------
// K3: conv3 (3x3, 16->31) + ReLU + pool -> g_x3 (packed) + g_x3p (padded)
// 512 blocks: (batch, 4x8 pooled tile). 128 threads = 32 px x 4 cog (8 co each).
// ---------------------------------------------------------------------------
__global__ __launch_bounds__(128) void k_conv3(
    const float* __restrict__ k3,      // (3,3,16,31)
    const float* __restrict__ b3)      // (31,)
{
    __shared__ __align__(16) float s_in[10 * 18 * 16];  // 2880 floats
    __shared__ __align__(16) float s_w[9 * 16 * 32];    // 4608 floats (co padded)
    __shared__ float s_b[32];

    int tid = threadIdx.x;
    int bidx = blockIdx.x;
    int b  = bidx >> 5;
    int t  = bidx & 31;                 // 8 ty-tiles x 4 tx-tiles
    int ty0 = (t >> 2) * 4;
    int tx0 = (t & 3) * 8;

    for (int i = tid; i < 4608; i += 128) {
        int tap = i >> 9;
        int rem = i & 511;
        int ci = rem >> 5, co = rem & 31;
        s_w[i] = (co < 31) ? k3[tap * 496 + ci * 31 + co] : 0.f;
    }
    if (tid < 32) s_b[tid] = (tid < 31) ? b3[tid] : 0.f;

    int iy0 = 2 * ty0 - 1, ix0 = 2 * tx0 - 1;
    for (int p = tid; p < 10 * 18; p += 128) {
        int r = p / 18, c = p % 18;
        int gy = iy0 + r, gx = ix0 + c;
        float* dst = &s_in[p * 16];
        if (gy >= 0 && gy < 64 && gx >= 0 && gx < 64) {
            const float* src = g_x2 + ((size_t)(b * 64 + gy) * 64 + gx) * 16;
#pragma unroll
            for (int q = 0; q < 4; q++)
                *(float4*)(dst + q * 4) = *(const float4*)(src + q * 4);
        } else {
#pragma unroll
            for (int q = 0; q < 4; q++)
                *(float4*)(dst + q * 4) = make_float4(0, 0, 0, 0);
        }
    }
    __syncthreads();

    int pix = tid >> 2, cog = tid & 3, cb = cog * 8;
    int ly = pix >> 3, lx = pix & 7;

    unsigned long long acc2[4][4];
#pragma unroll
    for (int p = 0; p < 4; p++)
#pragma unroll
        for (int k = 0; k < 4; k++) acc2[p][k] = 0ull;

#pragma unroll
    for (int ky = 0; ky < 3; ky++) {
#pragma unroll
        for (int kx = 0; kx < 3; kx++) {
            const float* wtap = &s_w[(ky * 3 + kx) * 512 + cb];
#pragma unroll
            for (int ciq = 0; ciq < 4; ciq++) {
                float iv[4][4];
#pragma unroll
                for (int dy = 0; dy < 2; dy++) {
#pragma unroll
                    for (int dx = 0; dx < 2; dx++) {
                        float4 v = *(const float4*)&s_in[
                            ((2 * ly + dy + ky) * 18 + (2 * lx + dx + kx)) * 16 + ciq * 4];
                        int p = dy * 2 + dx;
                        iv[p][0] = v.x; iv[p][1] = v.y; iv[p][2] = v.z; iv[p][3] = v.w;
                    }
                }
#pragma unroll
                for (int c = 0; c < 4; c++) {
                    ulonglong2 w0 = *(const ulonglong2*)(wtap + (ciq * 4 + c) * 32);
                    ulonglong2 w1 = *(const ulonglong2*)(wtap + (ciq * 4 + c) * 32 + 4);
#pragma unroll
                    for (int p = 0; p < 4; p++) {
                        unsigned long long vv = pk2(iv[p][c], iv[p][c]);
                        fma2(acc2[p][0], vv, w0.x);
                        fma2(acc2[p][1], vv, w0.y);
                        fma2(acc2[p][2], vv, w1.x);
                        fma2(acc2[p][3], vv, w1.y);
                    }
                }
            }
        }
    }

    float m[8];
#pragma unroll
    for (int k = 0; k < 4; k++) {
        float2 p0 = upk2(acc2[0][k]), p1 = upk2(acc2[1][k]);
        float2 p2 = upk2(acc2[2][k]), p3 = upk2(acc2[3][k]);
        m[2 * k]     = fmaxf(fmaxf(p0.x, p1.x), fmaxf(p2.x, p3.x));
        m[2 * k + 1] = fmaxf(fmaxf(p0.y, p1.y), fmaxf(p2.y, p3.y));
    }

    int py = ty0 + ly, px = tx0 + lx;
    int cell = (b * 32 + py) * 32 + px;
    float* op  = g_x3  + (size_t)cell * 31;
    float* opp = g_x3p + (size_t)cell * 32;
    if (cog == 0) opp[0] = 0.f;
#pragma unroll
    for (int k = 0; k < 8; k++) {
        int co = cb + k;
        if (co < 31) {
            float v = fmaxf(m[k] + s_b[co], 0.f);
            op[co] = v;
            opp[co + 1] = v;
        }
    }
}

// ---------------------------------------------------------------------------
// K5: d1 split-K with fused BN affine. 992 blocks, 32-feature slices.
// ---------------------------------------------------------------------------
__global__ __launch_bounds__(256) void k_d1(
    const float* __restrict__ d1k,
    const float* __restrict__ gamma, const float* __restrict__ beta,
    const float* __restrict__ mean,  const float* __restrict__ var)
{
    __shared__ __align__(16) float ks[32 * 64];   // 8 KB
    __shared__ __align__(16) float gs[16 * 32];   // 2 KB
    __shared__ float s_sc[32], s_sh[32];
    int tid = threadIdx.x;
    int p = blockIdx.x;

    const float4* kbase = (const float4*)(d1k + (size_t)p * 2048);
    float4* ks4 = (float4*)ks;
    ks4[tid]       = kbase[tid];
    ks4[tid + 256] = kbase[tid + 256];

    if (tid < 32) {
        int f = p * 32 + tid;
        float sc = rsqrtf(var[f] + BN_EPS) * gamma[f];
        s_sc[tid] = sc;
        s_sh[tid] = beta[f] - mean[f] * sc;
    }
    __syncthreads();
    for (int i = tid; i < 512; i += 256) {
        int bb = i >> 5, ii = i & 31;
        gs[i] = g_x3[bb * 31744 + p * 32 + ii] * s_sc[ii] + s_sh[ii];
    }
    __syncthreads();

    int j = tid & 63, bq = tid >> 6;
    float a0 = 0.f, a1 = 0.f, a2 = 0.f, a3 = 0.f;
#pragma unroll 8
    for (int i = 0; i < 32; i++) {
        float kv = ks[i * 64 + j];
        a0 += gs[bq * 32 + i]        * kv;
        a1 += gs[(bq + 4) * 32 + i]  * kv;
        a2 += gs[(bq + 8) * 32 + i]  * kv;
        a3 += gs[(bq + 12) * 32 + i] * kv;
    }
    g_part[((size_t)p * 16 + bq)      * 64 + j] = a0;
    g_part[((size_t)p * 16 + bq + 4)  * 64 + j] = a1;
    g_part[((size_t)p * 16 + bq + 8)  * 64 + j] = a2;
    g_part[((size_t)p * 16 + bq + 12) * 64 + j] = a3;
}

// ---------------------------------------------------------------------------
// K6: fused head — reduce d1 partials + bias + relu, then d2 + relu, then d3.
// One block per batch (16 blocks, 256 threads).
// ---------------------------------------------------------------------------
__global__ __launch_bounds__(256) void k_head(
    const float* __restrict__ d1b,
    const float* __restrict__ d2k, const float* __restrict__ d2b,
    const float* __restrict__ d3k, const float* __restrict__ d3b)
{
    __shared__ float s_red[256];
    __shared__ float h1s[64];
    __shared__ float h2s[96];
    int tid = threadIdx.x;
    int b = blockIdx.x;
    int j = tid & 63, grp = tid >> 6;

    float s = 0.f;
    for (int p = grp; p < 992; p += 4)
        s += g_part[((size_t)p * 16 + b) * 64 + j];
    s_red[tid] = s;
    __syncthreads();

    if (tid < 64) {
        float v = s_red[tid] + s_red[tid + 64] + s_red[tid + 128] + s_red[tid + 192];
        h1s[tid] = fmaxf(v + d1b[tid], 0.f);
    }
    __syncthreads();

    if (tid < 96) {
        float v = d2b[tid];
#pragma unroll 8
        for (int i = 0; i < 64; i++) v += h1s[i] * d2k[i * 96 + tid];
        h2s[tid] = fmaxf(v, 0.f);
    }
    __syncthreads();

    if (tid < 6) {
        float v = d3b[tid];
#pragma unroll 8
        for (int k = 0; k < 96; k++) v += h2s[k] * d3k[k * 6 + tid];
        g_theta[b * 6 + tid] = v;
    }
}

// ---------------------------------------------------------------------------
// K7: fused grid-gen + bilinear sampler + leaky relu.
// Block = 32 px along x, 4 consecutive rows. 8 lanes per pixel (channel quads).
// Per thread: 4 rows with fresh per-row coords (theta/setup amortized x4).
// ---------------------------------------------------------------------------
__global__ __launch_bounds__(256) void k_sampler(
    const float* __restrict__ x,       // (16,256,256,1)
    float* __restrict__ out)           // (16,256,256,32)
{
    int bidx = blockIdx.x;             // 8192 = 16 b x 64 row-groups x 8 col-groups
    int b   = bidx >> 9;
    int r   = bidx & 511;
    int oy0 = (r >> 3) * 4;
    int ox0 = (r & 7) * 32;
    int tid = threadIdx.x;
    int tq = tid & 7;                  // channel quad
    int pp = tid >> 3;                 // 0..31
    int ox = ox0 + pp;

    float th0 = g_theta[b * 6 + 0];
    float th1 = g_theta[b * 6 + 1];
    float th2 = g_theta[b * 6 + 2];
    float th3 = g_theta[b * 6 + 3];
    float th4 = g_theta[b * 6 + 4];
    float th5 = g_theta[b * 6 + 5];

    float gx = ((float)ox / 255.f) * 2.f - 1.f;
    const float* xb = x + (size_t)b * 65536;
    const float* xp = g_x3p + (size_t)b * 32768 + 4 * tq;

#pragma unroll
    for (int rr = 0; rr < 4; rr++) {
        int oy = oy0 + rr;
        float gy = ((float)oy / 255.f) * 2.f - 1.f;
        float tgx = gx * th0 + gy * th3 + th2;
        float tgy = gx * th1 + gy * th4 + th5;

        float fx = 0.5f * ((tgx + 1.f) * 255.f);
        float fy = 0.5f * ((tgy + 1.f) * 255.f);
        float x0f = floorf(fx), x1f = x0f + 1.f;
        float y0f = floorf(fy), y1f = y0f + 1.f;
        x0f = fminf(fmaxf(x0f, 0.f), 255.f);
        x1f = fminf(fmaxf(x1f, 0.f), 255.f);
        y0f = fminf(fmaxf(y0f, 0.f), 255.f);
        y1f = fminf(fmaxf(y1f, 0.f), 255.f);
        float wa = (x1f - fx) * (y1f - fy);
        float wb = (x1f - fx) * (fy - y0f);
        float wc = (fx - x0f) * (y1f - fy);
        float wd = (fx - x0f) * (fy - y0f);
        int xi0 = (int)x0f, xi1 = (int)x1f, yi0 = (int)y0f, yi1 = (int)y1f;

        int cy0 = yi0 >> 3, cy1 = yi1 >> 3, cx0 = xi0 >> 3, cx1 = xi1 >> 3;

        float4 va = *(const float4*)(xp + (cy0 * 32 + cx0) * 32);
        float4 vb = *(const float4*)(xp + (cy1 * 32 + cx0) * 32);
        float4 vc = *(const float4*)(xp + (cy0 * 32 + cx1) * 32);
        float4 vd = *(const float4*)(xp + (cy1 * 32 + cx1) * 32);

        float4 val;
        val.x = wa * va.x + wb * vb.x + wc * vc.x + wd * vd.x;
        val.y = wa * va.y + wb * vb.y + wc * vc.y + wd * vd.y;
        val.z = wa * va.z + wb * vb.z + wc * vc.z + wd * vd.z;
        val.w = wa * va.w + wb * vb.w + wc * vc.w + wd * vd.w;

        if (tq == 0) {
            val.x = wa * xb[yi0 * 256 + xi0] + wb * xb[yi1 * 256 + xi0]
                  + wc * xb[yi0 * 256 + xi1] + wd * xb[yi1 * 256 + xi1];
        }

        val.x = (val.x >= 0.f) ? val.x : 0.1f * val.x;
        val.y = (val.y >= 0.f) ? val.y : 0.1f * val.y;
        val.z = (val.z >= 0.f) ? val.z : 0.1f * val.z;
        val.w = (val.w >= 0.f) ? val.w : 0.1f * val.w;

        *(float4*)(out + (((size_t)(b * 256 + oy)) * 256 + ox) * 32 + 4 * tq) = val;
    }
}

// ---------------------------------------------------------------------------
// Launch
// ---------------------------------------------------------------------------
extern "C" void kernel_launch(void* const* d_in, const int* in_sizes, int n_in,
                              void* d_out, int out_size)
{
    const float* x       = (const float*)d_in[0];
    const float* conv1_k = (const float*)d_in[1];
    const float* conv1_b = (const float*)d_in[2];
    const float* conv2_k = (const float*)d_in[3];
    const float* conv2_b = (const float*)d_in[4];
    const float* conv3_k = (const float*)d_in[5];
    const float* conv3_b = (const float*)d_in[6];
    const float* bn_gamma = (const float*)d_in[7];
    const float* bn_beta  = (const float*)d_in[8];
    const float* bn_mean  = (const float*)d_in[9];
    const float* bn_var   = (const float*)d_in[10];
    const float* d1_k = (const float*)d_in[11];
    const float* d1_b = (const float*)d_in[12];
    const float* d2_k = (const float*)d_in[13];
    const float* d2_b = (const float*)d_in[14];
    const float* d3_k = (const float*)d_in[15];
    const float* d3_b = (const float*)d_in[16];
    float* out = (float*)d_out;

    k_conv1<<<1024, 256>>>(x, conv1_k, conv1_b);
    k_conv2<<<512, 256>>>(conv2_k, conv2_b);
    k_conv3<<<512, 128>>>(conv3_k, conv3_b);
    k_d1<<<992, 256>>>(d1_k, bn_gamma, bn_beta, bn_mean, bn_var);
    k_head<<<16, 256>>>(d1_b, d2_k, d2_b, d3_k, d3_b);
    k_d23_dummy: ;
    k_sampler<<<8192, 256>>>(x, out);
}